// round 1
// baseline (speedup 1.0000x reference)
#include <cuda_runtime.h>
#include <cuda_bf16.h>

#define B_   2
#define S_   2048
#define H_   1024
#define NH_  16
#define D_   64

// Scratch Q/K/V in head-major layout [b, h, s, d] (16 MB each)
__device__ __align__(16) float g_Q[B_ * NH_ * S_ * D_];
__device__ __align__(16) float g_K[B_ * NH_ * S_ * D_];
__device__ __align__(16) float g_V[B_ * NH_ * S_ * D_];

// ---------------------------------------------------------------------------
// QKV projection: out = X @ W + bias, X:[4096,1024], W:[1024,1024] row-major.
// Classic 128x128x8 sgemm, 256 threads, 8x8 microtile per thread.
// Output written head-major into g_Q / g_K / g_V (selected by `which`).
// ---------------------------------------------------------------------------
__global__ __launch_bounds__(256) void qkv_gemm(
    const float* __restrict__ X, const float* __restrict__ W,
    const float* __restrict__ bias, int which)
{
    __shared__ float As[8][132];   // [k][m], padded
    __shared__ float Bs[8][132];   // [k][n], padded

    const int tid  = threadIdx.x;
    const int tx   = tid & 15;
    const int ty   = tid >> 4;
    const int row0 = blockIdx.y * 128;
    const int col0 = blockIdx.x * 128;

    float acc[8][8];
#pragma unroll
    for (int i = 0; i < 8; i++)
#pragma unroll
        for (int j = 0; j < 8; j++) acc[i][j] = 0.f;

    const int ar = tid >> 1;          // 0..127 (A row)
    const int ak = (tid & 1) * 4;     // 0 or 4 (A k-offset)
    const int bk = tid >> 5;          // 0..7   (B k-row)
    const int bc = (tid & 31) * 4;    // 0..124 (B col)

    for (int k0 = 0; k0 < H_; k0 += 8) {
        float4 av = *reinterpret_cast<const float4*>(&X[(row0 + ar) * H_ + k0 + ak]);
        float4 bv = *reinterpret_cast<const float4*>(&W[(k0 + bk) * H_ + col0 + bc]);
        As[ak + 0][ar] = av.x;
        As[ak + 1][ar] = av.y;
        As[ak + 2][ar] = av.z;
        As[ak + 3][ar] = av.w;
        *reinterpret_cast<float4*>(&Bs[bk][bc]) = bv;
        __syncthreads();
#pragma unroll
        for (int kk = 0; kk < 8; kk++) {
            float a[8], b[8];
            *reinterpret_cast<float4*>(&a[0]) = *reinterpret_cast<const float4*>(&As[kk][ty * 8]);
            *reinterpret_cast<float4*>(&a[4]) = *reinterpret_cast<const float4*>(&As[kk][ty * 8 + 4]);
            *reinterpret_cast<float4*>(&b[0]) = *reinterpret_cast<const float4*>(&Bs[kk][tx * 8]);
            *reinterpret_cast<float4*>(&b[4]) = *reinterpret_cast<const float4*>(&Bs[kk][tx * 8 + 4]);
#pragma unroll
            for (int i = 0; i < 8; i++)
#pragma unroll
                for (int j = 0; j < 8; j++)
                    acc[i][j] += a[i] * b[j];
        }
        __syncthreads();
    }

    float* out = (which == 0) ? g_Q : (which == 1) ? g_K : g_V;
#pragma unroll
    for (int i = 0; i < 8; i++) {
        int m = row0 + ty * 8 + i;
        int bb = m >> 11;       // batch
        int s  = m & 2047;      // seq pos
#pragma unroll
        for (int jv = 0; jv < 8; jv += 4) {
            int n    = col0 + tx * 8 + jv;
            int head = n >> 6;
            int dd   = n & 63;
            float4 r;
            r.x = acc[i][jv + 0] + bias[n + 0];
            r.y = acc[i][jv + 1] + bias[n + 1];
            r.z = acc[i][jv + 2] + bias[n + 2];
            r.w = acc[i][jv + 3] + bias[n + 3];
            *reinterpret_cast<float4*>(
                &out[(((size_t)(bb * NH_ + head) * S_ + s) * D_) + dd]) = r;
        }
    }
}

// ---------------------------------------------------------------------------
// Flash attention, fp32. One block per (q-tile of 64 rows, head, batch).
// 256 threads = 8 warps; warp w owns 8 query rows, each lane owns 2 key cols
// (lane, lane+32). K tile is XOR-swizzled by row so per-column float4 reads
// along d are conflict-free; the K buffer is reused for P after scores.
// ---------------------------------------------------------------------------
__global__ __launch_bounds__(256) void attention(
    const float* __restrict__ mask, float* __restrict__ out)
{
    __shared__ float Qs[64][64];
    __shared__ float KP[64][64];   // K (swizzled), then P (linear)
    __shared__ float Vs[64][64];

    const int tid  = threadIdx.x;
    const int w    = tid >> 5;
    const int lane = tid & 31;
    const int qt   = blockIdx.x;
    const int head = blockIdx.y;
    const int b    = blockIdx.z;

    const float* Qg = g_Q + ((size_t)(b * NH_ + head) * S_ + qt * 64) * D_;
    const float* Kg = g_K + (size_t)(b * NH_ + head) * S_ * D_;
    const float* Vg = g_V + (size_t)(b * NH_ + head) * S_ * D_;
    const float* mk = mask + (size_t)b * S_;

    // Load the Q tile once
    {
        int r  = tid >> 2;
        int cc = (tid & 3) * 16;
#pragma unroll
        for (int c = 0; c < 16; c += 4)
            *reinterpret_cast<float4*>(&Qs[r][cc + c]) =
                *reinterpret_cast<const float4*>(&Qg[r * 64 + cc + c]);
    }

    float o0[8], o1[8], mrow[8], lrow[8];
#pragma unroll
    for (int i = 0; i < 8; i++) { o0[i] = 0.f; o1[i] = 0.f; mrow[i] = -1e30f; lrow[i] = 0.f; }

    const int c0 = lane;
    const int c1 = lane + 32;

    for (int t = 0; t < 32; t++) {
        __syncthreads();   // previous PV done with KP/Vs (also orders the Q store at t=0)

        // Load K (XOR-swizzled) and V tiles
        {
            int r  = tid >> 2;
            int q0 = (tid & 3) * 4;
            const float* kp = Kg + (size_t)(t * 64 + r) * 64;
            const float* vp = Vg + (size_t)(t * 64 + r) * 64;
#pragma unroll
            for (int qq = 0; qq < 4; qq++) {
                int lq = q0 + qq;                    // logical quad 0..15
                float4 kv = *reinterpret_cast<const float4*>(&kp[lq * 4]);
                int pq = lq ^ (r & 15);              // swizzled quad
                *reinterpret_cast<float4*>(&KP[r][pq * 4]) = kv;
                *reinterpret_cast<float4*>(&Vs[r][lq * 4]) =
                    *reinterpret_cast<const float4*>(&vp[lq * 4]);
            }
        }
        __syncthreads();

        // Scores S = Q K^T for this tile
        float s0[8], s1[8];
#pragma unroll
        for (int i = 0; i < 8; i++) { s0[i] = 0.f; s1[i] = 0.f; }
#pragma unroll
        for (int kk = 0; kk < 64; kk += 4) {
            int kq = kk >> 2;
            float4 k0 = *reinterpret_cast<const float4*>(&KP[c0][(kq ^ (c0 & 15)) * 4]);
            float4 k1 = *reinterpret_cast<const float4*>(&KP[c1][(kq ^ (c1 & 15)) * 4]);
#pragma unroll
            for (int i = 0; i < 8; i++) {
                float4 q = *reinterpret_cast<const float4*>(&Qs[w * 8 + i][kk]);
                s0[i] += q.x * k0.x + q.y * k0.y + q.z * k0.z + q.w * k0.w;
                s1[i] += q.x * k1.x + q.y * k1.y + q.z * k1.z + q.w * k1.w;
            }
        }
        float m0 = __ldg(&mk[t * 64 + c0]);
        float m1 = __ldg(&mk[t * 64 + c1]);

        __syncthreads();   // everyone done reading KP as K before P writes

        // Online softmax update; write P into KP
#pragma unroll
        for (int i = 0; i < 8; i++) {
            float a0 = s0[i] * 0.125f + m0;   // 1/sqrt(64)
            float a1 = s1[i] * 0.125f + m1;
            float tm = fmaxf(a0, a1);
#pragma unroll
            for (int off = 16; off > 0; off >>= 1)
                tm = fmaxf(tm, __shfl_xor_sync(0xffffffffu, tm, off));
            float mn    = fmaxf(mrow[i], tm);
            float alpha = __expf(mrow[i] - mn);
            mrow[i] = mn;
            float p0 = __expf(a0 - mn);
            float p1 = __expf(a1 - mn);
            float rs = p0 + p1;
#pragma unroll
            for (int off = 16; off > 0; off >>= 1)
                rs += __shfl_xor_sync(0xffffffffu, rs, off);
            lrow[i] = lrow[i] * alpha + rs;
            o0[i] *= alpha;
            o1[i] *= alpha;
            KP[w * 8 + i][c0] = p0;
            KP[w * 8 + i][c1] = p1;
        }
        __syncthreads();

        // O += P @ V
#pragma unroll
        for (int j = 0; j < 64; j += 4) {
            float v0[4], v1[4];
#pragma unroll
            for (int jj = 0; jj < 4; jj++) {
                v0[jj] = Vs[j + jj][c0];
                v1[jj] = Vs[j + jj][c1];
            }
#pragma unroll
            for (int i = 0; i < 8; i++) {
                float4 pp = *reinterpret_cast<const float4*>(&KP[w * 8 + i][j]);
                o0[i] += pp.x * v0[0] + pp.y * v0[1] + pp.z * v0[2] + pp.w * v0[3];
                o1[i] += pp.x * v1[0] + pp.y * v1[1] + pp.z * v1[2] + pp.w * v1[3];
            }
        }
    }

    // Epilogue: normalize and write [b, s, head*64 + d]
#pragma unroll
    for (int i = 0; i < 8; i++) {
        float inv = 1.0f / lrow[i];
        int row = qt * 64 + w * 8 + i;
        float* op = out + ((size_t)b * S_ + row) * H_ + head * D_;
        op[c0] = o0[i] * inv;
        op[c1] = o1[i] * inv;
    }
}

// ---------------------------------------------------------------------------
extern "C" void kernel_launch(void* const* d_in, const int* in_sizes, int n_in,
                              void* d_out, int out_size)
{
    const float* hs   = (const float*)d_in[0];
    const float* mask = (const float*)d_in[1];
    const float* Wq   = (const float*)d_in[2];
    const float* bq   = (const float*)d_in[3];
    const float* Wk   = (const float*)d_in[4];
    const float* bk   = (const float*)d_in[5];
    const float* Wv   = (const float*)d_in[6];
    const float* bv   = (const float*)d_in[7];
    float* out = (float*)d_out;

    dim3 ggemm(H_ / 128, (B_ * S_) / 128, 1);   // (8, 32)
    qkv_gemm<<<ggemm, 256>>>(hs, Wq, bq, 0);
    qkv_gemm<<<ggemm, 256>>>(hs, Wk, bk, 1);
    qkv_gemm<<<ggemm, 256>>>(hs, Wv, bv, 2);

    dim3 gattn(S_ / 64, NH_, B_);               // (32, 16, 2)
    attention<<<gattn, 256>>>(mask, out);
}

// round 2
// speedup vs baseline: 2.4312x; 2.4312x over previous
#include <cuda_runtime.h>
#include <cuda_bf16.h>
#include <cstdint>

#define B_   2
#define S_   2048
#define H_   1024
#define NH_  16
#define D_   64

// Scratch Q/K/V in head-major layout [b, h, s, d], fp32 (16 MB each)
__device__ __align__(16) float g_Q[B_ * NH_ * S_ * D_];
__device__ __align__(16) float g_K[B_ * NH_ * S_ * D_];
__device__ __align__(16) float g_V[B_ * NH_ * S_ * D_];

__device__ __forceinline__ uint32_t f2tf32(float f) {
    uint32_t r;
    asm("cvt.rna.tf32.f32 %0, %1;" : "=r"(r) : "f"(f));
    return r;
}

__device__ __forceinline__ void mma_tf32(float c[4], const uint32_t a[4],
                                         uint32_t b0, uint32_t b1) {
    asm volatile(
        "mma.sync.aligned.m16n8k8.row.col.f32.tf32.tf32.f32 "
        "{%0,%1,%2,%3}, {%4,%5,%6,%7}, {%8,%9}, {%0,%1,%2,%3};\n"
        : "+f"(c[0]), "+f"(c[1]), "+f"(c[2]), "+f"(c[3])
        : "r"(a[0]), "r"(a[1]), "r"(a[2]), "r"(a[3]), "r"(b0), "r"(b1));
}

// ---------------------------------------------------------------------------
// QKV projection: out = X @ W + bias (tf32 tensor-core sgemm).
// Block tile 128x128, K-chunk 32. 256 threads = 8 warps laid out 4(M) x 2(N);
// each warp owns a 32x64 tile = 2 m-tiles x 8 n-tiles of m16n8k8.
// ---------------------------------------------------------------------------
__global__ __launch_bounds__(256) void qkv_gemm(
    const float* __restrict__ X, const float* __restrict__ W,
    const float* __restrict__ bias, int which)
{
    __shared__ uint32_t As[128][36];   // [m][k], stride 36 -> (4g+tg)%32 distinct
    __shared__ uint32_t Bs[32][136];   // [k][n], stride 136 -> (8tg+g)%32 distinct

    const int tid   = threadIdx.x;
    const int wid   = tid >> 5;
    const int lane  = tid & 31;
    const int g     = lane >> 2;
    const int tg    = lane & 3;
    const int warpM = wid >> 1;        // 0..3
    const int warpN = wid & 1;         // 0..1
    const int row0  = blockIdx.y * 128;
    const int col0  = blockIdx.x * 128;

    float c[2][8][4];
#pragma unroll
    for (int mt = 0; mt < 2; mt++)
#pragma unroll
        for (int nt = 0; nt < 8; nt++)
#pragma unroll
            for (int j = 0; j < 4; j++) c[mt][nt][j] = 0.f;

    for (int k0 = 0; k0 < H_; k0 += 32) {
        // Load A tile 128x32 (4 passes of 256 float4)
#pragma unroll
        for (int p = 0; p < 4; p++) {
            int r  = (tid >> 3) + p * 32;
            int cc = (tid & 7) * 4;
            float4 v = *reinterpret_cast<const float4*>(&X[(size_t)(row0 + r) * H_ + k0 + cc]);
            As[r][cc + 0] = f2tf32(v.x);
            As[r][cc + 1] = f2tf32(v.y);
            As[r][cc + 2] = f2tf32(v.z);
            As[r][cc + 3] = f2tf32(v.w);
        }
        // Load B tile 32x128
#pragma unroll
        for (int p = 0; p < 4; p++) {
            int k  = (tid >> 5) + p * 8;
            int n  = (tid & 31) * 4;
            float4 v = *reinterpret_cast<const float4*>(&W[(size_t)(k0 + k) * H_ + col0 + n]);
            Bs[k][n + 0] = f2tf32(v.x);
            Bs[k][n + 1] = f2tf32(v.y);
            Bs[k][n + 2] = f2tf32(v.z);
            Bs[k][n + 3] = f2tf32(v.w);
        }
        __syncthreads();

#pragma unroll
        for (int kk = 0; kk < 4; kk++) {
            int k = kk * 8;
            uint32_t a[2][4], b[8][2];
#pragma unroll
            for (int mt = 0; mt < 2; mt++) {
                int rb = warpM * 32 + mt * 16;
                a[mt][0] = As[rb + g][k + tg];
                a[mt][1] = As[rb + g + 8][k + tg];
                a[mt][2] = As[rb + g][k + tg + 4];
                a[mt][3] = As[rb + g + 8][k + tg + 4];
            }
#pragma unroll
            for (int nt = 0; nt < 8; nt++) {
                int nb = warpN * 64 + nt * 8;
                b[nt][0] = Bs[k + tg][nb + g];
                b[nt][1] = Bs[k + tg + 4][nb + g];
            }
#pragma unroll
            for (int mt = 0; mt < 2; mt++)
#pragma unroll
                for (int nt = 0; nt < 8; nt++)
                    mma_tf32(c[mt][nt], a[mt], b[nt][0], b[nt][1]);
        }
        __syncthreads();
    }

    // Epilogue: bias add (fp32) + head-major scatter
    float* out = (which == 0) ? g_Q : (which == 1) ? g_K : g_V;
    const int head = ((col0 + warpN * 64) >> 6);   // constant per warp
#pragma unroll
    for (int mt = 0; mt < 2; mt++) {
#pragma unroll
        for (int nt = 0; nt < 8; nt++) {
            int dd   = nt * 8 + 2 * tg;
            int coln = col0 + warpN * 64 + dd;
            float b0 = bias[coln], b1 = bias[coln + 1];
            int r0 = row0 + warpM * 32 + mt * 16 + g;
            int r1 = r0 + 8;
            int bb0 = r0 >> 11, s0 = r0 & 2047;
            int bb1 = r1 >> 11, s1 = r1 & 2047;
            float2 v0 = {c[mt][nt][0] + b0, c[mt][nt][1] + b1};
            float2 v1 = {c[mt][nt][2] + b0, c[mt][nt][3] + b1};
            *reinterpret_cast<float2*>(
                &out[(((size_t)(bb0 * NH_ + head) * S_ + s0) * D_) + dd]) = v0;
            *reinterpret_cast<float2*>(
                &out[(((size_t)(bb1 * NH_ + head) * S_ + s1) * D_) + dd]) = v1;
        }
    }
}

// ---------------------------------------------------------------------------
// Flash attention, tf32 tensor cores. One block (128 thr = 4 warps) per
// (64-row q-tile, head, batch). Warp w owns q rows w*16..w*16+15.
// K smem buffer is reused for P between the two MMAs (warp-local rows).
// ---------------------------------------------------------------------------
__global__ __launch_bounds__(128) void attention(
    const float* __restrict__ mask, float* __restrict__ out)
{
    extern __shared__ float sm[];
    uint32_t* Qs  = reinterpret_cast<uint32_t*>(sm);            // [64][68]
    uint32_t* KP  = reinterpret_cast<uint32_t*>(sm) + 4352;     // [64][68] K then P
    uint32_t* Vs  = reinterpret_cast<uint32_t*>(sm) + 8704;     // [64][72]
    float*    msk = sm + 13312;                                  // [2048]

    const int tid  = threadIdx.x;
    const int w    = tid >> 5;
    const int lane = tid & 31;
    const int g    = lane >> 2;
    const int tg   = lane & 3;
    const int rb   = w * 16;
    const int qt   = blockIdx.x;
    const int head = blockIdx.y;
    const int b    = blockIdx.z;

    const float* Qg = g_Q + ((size_t)(b * NH_ + head) * S_ + qt * 64) * D_;
    const float* Kg = g_K + (size_t)(b * NH_ + head) * S_ * D_;
    const float* Vg = g_V + (size_t)(b * NH_ + head) * S_ * D_;

    // Stage Q tile (tf32) and the full mask row (fp32)
    {
        int r  = tid >> 1;
        int cc = (tid & 1) * 32;
#pragma unroll
        for (int i = 0; i < 8; i++) {
            float4 v = *reinterpret_cast<const float4*>(&Qg[(size_t)r * 64 + cc + i * 4]);
            Qs[r * 68 + cc + i * 4 + 0] = f2tf32(v.x);
            Qs[r * 68 + cc + i * 4 + 1] = f2tf32(v.y);
            Qs[r * 68 + cc + i * 4 + 2] = f2tf32(v.z);
            Qs[r * 68 + cc + i * 4 + 3] = f2tf32(v.w);
        }
    }
    for (int i = tid; i < S_; i += 128) msk[i] = mask[(size_t)b * S_ + i];

    float o[8][4];
#pragma unroll
    for (int nt = 0; nt < 8; nt++)
#pragma unroll
        for (int j = 0; j < 4; j++) o[nt][j] = 0.f;
    float m0 = -1e30f, m1 = -1e30f, l0 = 0.f, l1 = 0.f;

    for (int t = 0; t < 32; t++) {
        __syncthreads();   // prior iter done with KP(P) / Vs; also orders Q/msk staging

        // Load K (-> KP) and V tiles, converting to tf32
        {
            int r  = tid >> 1;
            int cc = (tid & 1) * 32;
            const float* kp = Kg + (size_t)(t * 64 + r) * 64;
            const float* vp = Vg + (size_t)(t * 64 + r) * 64;
#pragma unroll
            for (int i = 0; i < 8; i++) {
                float4 kv = *reinterpret_cast<const float4*>(&kp[cc + i * 4]);
                float4 vv = *reinterpret_cast<const float4*>(&vp[cc + i * 4]);
                KP[r * 68 + cc + i * 4 + 0] = f2tf32(kv.x);
                KP[r * 68 + cc + i * 4 + 1] = f2tf32(kv.y);
                KP[r * 68 + cc + i * 4 + 2] = f2tf32(kv.z);
                KP[r * 68 + cc + i * 4 + 3] = f2tf32(kv.w);
                Vs[r * 72 + cc + i * 4 + 0] = f2tf32(vv.x);
                Vs[r * 72 + cc + i * 4 + 1] = f2tf32(vv.y);
                Vs[r * 72 + cc + i * 4 + 2] = f2tf32(vv.z);
                Vs[r * 72 + cc + i * 4 + 3] = f2tf32(vv.w);
            }
        }
        __syncthreads();

        // ---- Scores: S = Q @ K^T  (warp rows rb..rb+15, all 64 key cols)
        uint32_t aq[8][4];
#pragma unroll
        for (int kk = 0; kk < 8; kk++) {
            int k = kk * 8;
            aq[kk][0] = Qs[(rb + g) * 68 + k + tg];
            aq[kk][1] = Qs[(rb + g + 8) * 68 + k + tg];
            aq[kk][2] = Qs[(rb + g) * 68 + k + tg + 4];
            aq[kk][3] = Qs[(rb + g + 8) * 68 + k + tg + 4];
        }
        float s[8][4];
#pragma unroll
        for (int nt = 0; nt < 8; nt++)
#pragma unroll
            for (int j = 0; j < 4; j++) s[nt][j] = 0.f;
#pragma unroll
        for (int nt = 0; nt < 8; nt++) {
            int n0 = nt * 8;
#pragma unroll
            for (int kk = 0; kk < 8; kk++) {
                uint32_t b0 = KP[(n0 + g) * 68 + kk * 8 + tg];
                uint32_t b1 = KP[(n0 + g) * 68 + kk * 8 + tg + 4];
                mma_tf32(s[nt], aq[kk], b0, b1);
            }
        }
        __syncthreads();   // all warps done reading KP as K

        // ---- Online softmax (rows rb+g and rb+g+8; state replicated over tg group)
        float rm0 = -1e30f, rm1 = -1e30f;
#pragma unroll
        for (int nt = 0; nt < 8; nt++) {
            float mk0 = msk[t * 64 + nt * 8 + 2 * tg];
            float mk1 = msk[t * 64 + nt * 8 + 2 * tg + 1];
            s[nt][0] = s[nt][0] * 0.125f + mk0;
            s[nt][1] = s[nt][1] * 0.125f + mk1;
            s[nt][2] = s[nt][2] * 0.125f + mk0;
            s[nt][3] = s[nt][3] * 0.125f + mk1;
            rm0 = fmaxf(rm0, fmaxf(s[nt][0], s[nt][1]));
            rm1 = fmaxf(rm1, fmaxf(s[nt][2], s[nt][3]));
        }
        rm0 = fmaxf(rm0, __shfl_xor_sync(0xffffffffu, rm0, 1));
        rm0 = fmaxf(rm0, __shfl_xor_sync(0xffffffffu, rm0, 2));
        rm1 = fmaxf(rm1, __shfl_xor_sync(0xffffffffu, rm1, 1));
        rm1 = fmaxf(rm1, __shfl_xor_sync(0xffffffffu, rm1, 2));
        float mn0 = fmaxf(m0, rm0), mn1 = fmaxf(m1, rm1);
        float al0 = __expf(m0 - mn0), al1 = __expf(m1 - mn1);
        m0 = mn0; m1 = mn1;
        float rs0 = 0.f, rs1 = 0.f;
#pragma unroll
        for (int nt = 0; nt < 8; nt++) {
            s[nt][0] = __expf(s[nt][0] - mn0);
            s[nt][1] = __expf(s[nt][1] - mn0);
            s[nt][2] = __expf(s[nt][2] - mn1);
            s[nt][3] = __expf(s[nt][3] - mn1);
            rs0 += s[nt][0] + s[nt][1];
            rs1 += s[nt][2] + s[nt][3];
        }
        rs0 += __shfl_xor_sync(0xffffffffu, rs0, 1);
        rs0 += __shfl_xor_sync(0xffffffffu, rs0, 2);
        rs1 += __shfl_xor_sync(0xffffffffu, rs1, 1);
        rs1 += __shfl_xor_sync(0xffffffffu, rs1, 2);
        l0 = l0 * al0 + rs0;
        l1 = l1 * al1 + rs1;
#pragma unroll
        for (int nt = 0; nt < 8; nt++) {
            o[nt][0] *= al0; o[nt][1] *= al0;
            o[nt][2] *= al1; o[nt][3] *= al1;
        }

        // Write P (tf32) into this warp's own KP rows (warp-local reuse)
#pragma unroll
        for (int nt = 0; nt < 8; nt++) {
            KP[(rb + g) * 68 + nt * 8 + 2 * tg]         = f2tf32(s[nt][0]);
            KP[(rb + g) * 68 + nt * 8 + 2 * tg + 1]     = f2tf32(s[nt][1]);
            KP[(rb + g + 8) * 68 + nt * 8 + 2 * tg]     = f2tf32(s[nt][2]);
            KP[(rb + g + 8) * 68 + nt * 8 + 2 * tg + 1] = f2tf32(s[nt][3]);
        }
        __syncwarp();

        // ---- O += P @ V
        uint32_t ap[8][4];
#pragma unroll
        for (int kk = 0; kk < 8; kk++) {
            int k = kk * 8;
            ap[kk][0] = KP[(rb + g) * 68 + k + tg];
            ap[kk][1] = KP[(rb + g + 8) * 68 + k + tg];
            ap[kk][2] = KP[(rb + g) * 68 + k + tg + 4];
            ap[kk][3] = KP[(rb + g + 8) * 68 + k + tg + 4];
        }
#pragma unroll
        for (int nt = 0; nt < 8; nt++) {
            int n0 = nt * 8;
#pragma unroll
            for (int kk = 0; kk < 8; kk++) {
                uint32_t b0 = Vs[(kk * 8 + tg) * 72 + n0 + g];
                uint32_t b1 = Vs[(kk * 8 + tg + 4) * 72 + n0 + g];
                mma_tf32(o[nt], ap[kk], b0, b1);
            }
        }
    }

    // ---- Epilogue: normalize, write [b, s, head*64 + d]
    float inv0 = 1.0f / l0, inv1 = 1.0f / l1;
    int r0 = qt * 64 + rb + g;
    int r1 = r0 + 8;
#pragma unroll
    for (int nt = 0; nt < 8; nt++) {
        int dd = nt * 8 + 2 * tg;
        float2 v0 = {o[nt][0] * inv0, o[nt][1] * inv0};
        float2 v1 = {o[nt][2] * inv1, o[nt][3] * inv1};
        *reinterpret_cast<float2*>(&out[((size_t)b * S_ + r0) * H_ + head * D_ + dd]) = v0;
        *reinterpret_cast<float2*>(&out[((size_t)b * S_ + r1) * H_ + head * D_ + dd]) = v1;
    }
}

// ---------------------------------------------------------------------------
extern "C" void kernel_launch(void* const* d_in, const int* in_sizes, int n_in,
                              void* d_out, int out_size)
{
    const float* hs   = (const float*)d_in[0];
    const float* mask = (const float*)d_in[1];
    const float* Wq   = (const float*)d_in[2];
    const float* bq   = (const float*)d_in[3];
    const float* Wk   = (const float*)d_in[4];
    const float* bk   = (const float*)d_in[5];
    const float* Wv   = (const float*)d_in[6];
    const float* bv   = (const float*)d_in[7];
    float* out = (float*)d_out;

    static bool attr_set = false;
    if (!attr_set) {
        cudaFuncSetAttribute(attention, cudaFuncAttributeMaxDynamicSharedMemorySize, 61440);
        attr_set = true;
    }

    dim3 ggemm(H_ / 128, (B_ * S_) / 128, 1);   // (8, 32)
    qkv_gemm<<<ggemm, 256>>>(hs, Wq, bq, 0);
    qkv_gemm<<<ggemm, 256>>>(hs, Wk, bk, 1);
    qkv_gemm<<<ggemm, 256>>>(hs, Wv, bv, 2);

    dim3 gattn(S_ / 64, NH_, B_);               // (32, 16, 2)
    attention<<<gattn, 128, 61440>>>(mask, out);
}

// round 3
// speedup vs baseline: 4.0406x; 1.6620x over previous
#include <cuda_runtime.h>
#include <cuda_bf16.h>
#include <cstdint>

#define B_   2
#define S_   2048
#define H_   1024
#define NH_  16
#define D_   64

// Scratch Q/K/V in head-major layout [b, h, s, d], fp32 (16 MB each)
__device__ __align__(16) float g_Q[B_ * NH_ * S_ * D_];
__device__ __align__(16) float g_K[B_ * NH_ * S_ * D_];
__device__ __align__(16) float g_V[B_ * NH_ * S_ * D_];

__device__ __forceinline__ uint32_t f2tf32(float f) {
    uint32_t r;
    asm("cvt.rna.tf32.f32 %0, %1;" : "=r"(r) : "f"(f));
    return r;
}

__device__ __forceinline__ void mma_tf32(float c[4], const uint32_t a[4],
                                         uint32_t b0, uint32_t b1) {
    asm volatile(
        "mma.sync.aligned.m16n8k8.row.col.f32.tf32.tf32.f32 "
        "{%0,%1,%2,%3}, {%4,%5,%6,%7}, {%8,%9}, {%0,%1,%2,%3};\n"
        : "+f"(c[0]), "+f"(c[1]), "+f"(c[2]), "+f"(c[3])
        : "r"(a[0]), "r"(a[1]), "r"(a[2]), "r"(a[3]), "r"(b0), "r"(b1));
}

// ---------------------------------------------------------------------------
// Fused QKV projection: out = X @ W + bias (tf32 mma), W selected by blockIdx.z.
// Block tile 128x128, K-chunk 32. 256 threads = 8 warps (4M x 2N), warp tile
// 32x64 = 2 m-tiles x 8 n-tiles of m16n8k8.
// ---------------------------------------------------------------------------
__global__ __launch_bounds__(256) void qkv_gemm(
    const float* __restrict__ X,
    const float* __restrict__ Wq, const float* __restrict__ Wk,
    const float* __restrict__ Wv,
    const float* __restrict__ bq, const float* __restrict__ bk,
    const float* __restrict__ bv)
{
    __shared__ uint32_t As[128][36];
    __shared__ uint32_t Bs[32][136];

    const float* W; const float* bias; float* out;
    if (blockIdx.z == 0)      { W = Wq; bias = bq; out = g_Q; }
    else if (blockIdx.z == 1) { W = Wk; bias = bk; out = g_K; }
    else                      { W = Wv; bias = bv; out = g_V; }

    const int tid   = threadIdx.x;
    const int wid   = tid >> 5;
    const int lane  = tid & 31;
    const int g     = lane >> 2;
    const int tg    = lane & 3;
    const int warpM = wid >> 1;
    const int warpN = wid & 1;
    const int row0  = blockIdx.y * 128;
    const int col0  = blockIdx.x * 128;

    float c[2][8][4];
#pragma unroll
    for (int mt = 0; mt < 2; mt++)
#pragma unroll
        for (int nt = 0; nt < 8; nt++)
#pragma unroll
            for (int j = 0; j < 4; j++) c[mt][nt][j] = 0.f;

    for (int k0 = 0; k0 < H_; k0 += 32) {
#pragma unroll
        for (int p = 0; p < 4; p++) {
            int r  = (tid >> 3) + p * 32;
            int cc = (tid & 7) * 4;
            float4 v = *reinterpret_cast<const float4*>(&X[(size_t)(row0 + r) * H_ + k0 + cc]);
            As[r][cc + 0] = f2tf32(v.x);
            As[r][cc + 1] = f2tf32(v.y);
            As[r][cc + 2] = f2tf32(v.z);
            As[r][cc + 3] = f2tf32(v.w);
        }
#pragma unroll
        for (int p = 0; p < 4; p++) {
            int k = (tid >> 5) + p * 8;
            int n = (tid & 31) * 4;
            float4 v = *reinterpret_cast<const float4*>(&W[(size_t)(k0 + k) * H_ + col0 + n]);
            Bs[k][n + 0] = f2tf32(v.x);
            Bs[k][n + 1] = f2tf32(v.y);
            Bs[k][n + 2] = f2tf32(v.z);
            Bs[k][n + 3] = f2tf32(v.w);
        }
        __syncthreads();

#pragma unroll
        for (int kk = 0; kk < 4; kk++) {
            int k = kk * 8;
            uint32_t a[2][4], b[8][2];
#pragma unroll
            for (int mt = 0; mt < 2; mt++) {
                int rb = warpM * 32 + mt * 16;
                a[mt][0] = As[rb + g][k + tg];
                a[mt][1] = As[rb + g + 8][k + tg];
                a[mt][2] = As[rb + g][k + tg + 4];
                a[mt][3] = As[rb + g + 8][k + tg + 4];
            }
#pragma unroll
            for (int nt = 0; nt < 8; nt++) {
                int nb = warpN * 64 + nt * 8;
                b[nt][0] = Bs[k + tg][nb + g];
                b[nt][1] = Bs[k + tg + 4][nb + g];
            }
#pragma unroll
            for (int mt = 0; mt < 2; mt++)
#pragma unroll
                for (int nt = 0; nt < 8; nt++)
                    mma_tf32(c[mt][nt], a[mt], b[nt][0], b[nt][1]);
        }
        __syncthreads();
    }

    const int head = ((col0 + warpN * 64) >> 6);
#pragma unroll
    for (int mt = 0; mt < 2; mt++) {
#pragma unroll
        for (int nt = 0; nt < 8; nt++) {
            int dd   = nt * 8 + 2 * tg;
            int coln = col0 + warpN * 64 + dd;
            float b0 = bias[coln], b1 = bias[coln + 1];
            int r0 = row0 + warpM * 32 + mt * 16 + g;
            int r1 = r0 + 8;
            int bb0 = r0 >> 11, s0 = r0 & 2047;
            int bb1 = r1 >> 11, s1 = r1 & 2047;
            float2 v0 = {c[mt][nt][0] + b0, c[mt][nt][1] + b1};
            float2 v1 = {c[mt][nt][2] + b0, c[mt][nt][3] + b1};
            *reinterpret_cast<float2*>(
                &out[(((size_t)(bb0 * NH_ + head) * S_ + s0) * D_) + dd]) = v0;
            *reinterpret_cast<float2*>(
                &out[(((size_t)(bb1 * NH_ + head) * S_ + s1) * D_) + dd]) = v1;
        }
    }
}

// ---------------------------------------------------------------------------
// Flash attention, tf32. 128 q-rows per block, 4 warps x 32 rows (2 m-tiles).
// Every K/V b-fragment feeds 2 mmas. P never touches smem: score C-fragments
// are shuffle-transposed in registers into PV A-fragments.
// ---------------------------------------------------------------------------
__global__ __launch_bounds__(128) void attention(
    const float* __restrict__ mask, float* __restrict__ out)
{
    extern __shared__ uint32_t smu[];
    uint32_t* Qs  = smu;                    // [128][68]
    uint32_t* Ks  = smu + 8704;             // [64][68]
    uint32_t* Vs  = smu + 13056;            // [64][72]
    float*    msk = (float*)(smu + 17664);  // [2048]

    const int tid  = threadIdx.x;
    const int w    = tid >> 5;
    const int lane = tid & 31;
    const int g    = lane >> 2;
    const int tg   = lane & 3;
    const int rb   = w * 32;
    const int qt   = blockIdx.x;
    const int head = blockIdx.y;
    const int b    = blockIdx.z;

    const float* Qg = g_Q + ((size_t)(b * NH_ + head) * S_ + qt * 128) * D_;
    const float* Kg = g_K + (size_t)(b * NH_ + head) * S_ * D_;
    const float* Vg = g_V + (size_t)(b * NH_ + head) * S_ * D_;

    // Stage Q tile (tf32) — coalesced: 16 threads cover one 256B row
#pragma unroll
    for (int i = 0; i < 16; i++) {
        int r = i * 8 + (tid >> 4);
        int c = (tid & 15) * 4;
        float4 v = *reinterpret_cast<const float4*>(&Qg[(size_t)r * 64 + c]);
        uint4 u = {f2tf32(v.x), f2tf32(v.y), f2tf32(v.z), f2tf32(v.w)};
        *reinterpret_cast<uint4*>(&Qs[r * 68 + c]) = u;
    }
    // Stage mask row
    for (int i = tid; i < S_; i += 128) msk[i] = mask[(size_t)b * S_ + i];

    float o[2][8][4];
#pragma unroll
    for (int mt = 0; mt < 2; mt++)
#pragma unroll
        for (int nt = 0; nt < 8; nt++)
#pragma unroll
            for (int j = 0; j < 4; j++) o[mt][nt][j] = 0.f;
    float mx[2][2] = {{-1e30f, -1e30f}, {-1e30f, -1e30f}};
    float l[2][2]  = {{0.f, 0.f}, {0.f, 0.f}};

    const int src = (lane & ~3) | (tg >> 1);   // shuffle-transpose source lane
    const bool odd = tg & 1;

    for (int t = 0; t < 32; t++) {
        __syncthreads();   // prior tile done with Ks/Vs (covers Q/msk at t=0)

        // Stage K and V tiles (tf32)
#pragma unroll
        for (int i = 0; i < 8; i++) {
            int r = i * 8 + (tid >> 4);
            int c = (tid & 15) * 4;
            float4 kv = *reinterpret_cast<const float4*>(&Kg[(size_t)(t * 64 + r) * 64 + c]);
            float4 vv = *reinterpret_cast<const float4*>(&Vg[(size_t)(t * 64 + r) * 64 + c]);
            uint4 ku = {f2tf32(kv.x), f2tf32(kv.y), f2tf32(kv.z), f2tf32(kv.w)};
            uint4 vu = {f2tf32(vv.x), f2tf32(vv.y), f2tf32(vv.z), f2tf32(vv.w)};
            *reinterpret_cast<uint4*>(&Ks[r * 68 + c]) = ku;
            *reinterpret_cast<uint4*>(&Vs[r * 72 + c]) = vu;
        }
        __syncthreads();

        // ---- Scores: S = Q @ K^T for 32 rows (2 m-tiles), 64 key cols
        float s[2][8][4];
#pragma unroll
        for (int mt = 0; mt < 2; mt++)
#pragma unroll
            for (int nt = 0; nt < 8; nt++)
#pragma unroll
                for (int j = 0; j < 4; j++) s[mt][nt][j] = 0.f;

#pragma unroll
        for (int kk = 0; kk < 8; kk++) {
            int k = kk * 8;
            uint32_t a[2][4];
#pragma unroll
            for (int mt = 0; mt < 2; mt++) {
                int r = rb + mt * 16;
                a[mt][0] = Qs[(r + g) * 68 + k + tg];
                a[mt][1] = Qs[(r + g + 8) * 68 + k + tg];
                a[mt][2] = Qs[(r + g) * 68 + k + tg + 4];
                a[mt][3] = Qs[(r + g + 8) * 68 + k + tg + 4];
            }
#pragma unroll
            for (int nt = 0; nt < 8; nt++) {
                uint32_t b0 = Ks[(nt * 8 + g) * 68 + k + tg];
                uint32_t b1 = Ks[(nt * 8 + g) * 68 + k + tg + 4];
                mma_tf32(s[0][nt], a[0], b0, b1);
                mma_tf32(s[1][nt], a[1], b0, b1);
            }
        }

        // Mask values (shared across both m-tiles)
        float mk[8][2];
#pragma unroll
        for (int nt = 0; nt < 8; nt++) {
            float2 mv = *reinterpret_cast<const float2*>(&msk[t * 64 + nt * 8 + 2 * tg]);
            mk[nt][0] = mv.x; mk[nt][1] = mv.y;
        }

        // ---- Online softmax per m-tile
#pragma unroll
        for (int mt = 0; mt < 2; mt++) {
            float rm0 = -1e30f, rm1 = -1e30f;
#pragma unroll
            for (int nt = 0; nt < 8; nt++) {
                s[mt][nt][0] = s[mt][nt][0] * 0.125f + mk[nt][0];
                s[mt][nt][1] = s[mt][nt][1] * 0.125f + mk[nt][1];
                s[mt][nt][2] = s[mt][nt][2] * 0.125f + mk[nt][0];
                s[mt][nt][3] = s[mt][nt][3] * 0.125f + mk[nt][1];
                rm0 = fmaxf(rm0, fmaxf(s[mt][nt][0], s[mt][nt][1]));
                rm1 = fmaxf(rm1, fmaxf(s[mt][nt][2], s[mt][nt][3]));
            }
            rm0 = fmaxf(rm0, __shfl_xor_sync(0xffffffffu, rm0, 1));
            rm0 = fmaxf(rm0, __shfl_xor_sync(0xffffffffu, rm0, 2));
            rm1 = fmaxf(rm1, __shfl_xor_sync(0xffffffffu, rm1, 1));
            rm1 = fmaxf(rm1, __shfl_xor_sync(0xffffffffu, rm1, 2));
            float mn0 = fmaxf(mx[mt][0], rm0), mn1 = fmaxf(mx[mt][1], rm1);
            float al0 = __expf(mx[mt][0] - mn0), al1 = __expf(mx[mt][1] - mn1);
            mx[mt][0] = mn0; mx[mt][1] = mn1;
            float rs0 = 0.f, rs1 = 0.f;
#pragma unroll
            for (int nt = 0; nt < 8; nt++) {
                s[mt][nt][0] = __expf(s[mt][nt][0] - mn0);
                s[mt][nt][1] = __expf(s[mt][nt][1] - mn0);
                s[mt][nt][2] = __expf(s[mt][nt][2] - mn1);
                s[mt][nt][3] = __expf(s[mt][nt][3] - mn1);
                rs0 += s[mt][nt][0] + s[mt][nt][1];
                rs1 += s[mt][nt][2] + s[mt][nt][3];
            }
            rs0 += __shfl_xor_sync(0xffffffffu, rs0, 1);
            rs0 += __shfl_xor_sync(0xffffffffu, rs0, 2);
            rs1 += __shfl_xor_sync(0xffffffffu, rs1, 1);
            rs1 += __shfl_xor_sync(0xffffffffu, rs1, 2);
            l[mt][0] = l[mt][0] * al0 + rs0;
            l[mt][1] = l[mt][1] * al1 + rs1;
#pragma unroll
            for (int nt = 0; nt < 8; nt++) {
                o[mt][nt][0] *= al0; o[mt][nt][1] *= al0;
                o[mt][nt][2] *= al1; o[mt][nt][3] *= al1;
            }
        }

        // ---- O += P @ V  (P via in-register shuffle transpose of s)
#pragma unroll
        for (int kk = 0; kk < 8; kk++) {
            uint32_t ap[2][4];
#pragma unroll
            for (int mt = 0; mt < 2; mt++) {
                float e0 = __shfl_sync(0xffffffffu, s[mt][kk][0], src);
                float e1 = __shfl_sync(0xffffffffu, s[mt][kk][1], src);
                float e2 = __shfl_sync(0xffffffffu, s[mt][kk][2], src);
                float e3 = __shfl_sync(0xffffffffu, s[mt][kk][3], src);
                float f0 = __shfl_sync(0xffffffffu, s[mt][kk][0], src + 2);
                float f1 = __shfl_sync(0xffffffffu, s[mt][kk][1], src + 2);
                float f2 = __shfl_sync(0xffffffffu, s[mt][kk][2], src + 2);
                float f3 = __shfl_sync(0xffffffffu, s[mt][kk][3], src + 2);
                ap[mt][0] = f2tf32(odd ? e1 : e0);
                ap[mt][1] = f2tf32(odd ? e3 : e2);
                ap[mt][2] = f2tf32(odd ? f1 : f0);
                ap[mt][3] = f2tf32(odd ? f3 : f2);
            }
#pragma unroll
            for (int nt = 0; nt < 8; nt++) {
                uint32_t b0 = Vs[(kk * 8 + tg) * 72 + nt * 8 + g];
                uint32_t b1 = Vs[(kk * 8 + tg + 4) * 72 + nt * 8 + g];
                mma_tf32(o[0][nt], ap[0], b0, b1);
                mma_tf32(o[1][nt], ap[1], b0, b1);
            }
        }
    }

    // ---- Epilogue: normalize, write [b, s, head*64 + d]
#pragma unroll
    for (int mt = 0; mt < 2; mt++) {
        float i0 = 1.0f / l[mt][0], i1 = 1.0f / l[mt][1];
        int r0 = qt * 128 + rb + mt * 16 + g;
        int r1 = r0 + 8;
#pragma unroll
        for (int nt = 0; nt < 8; nt++) {
            int dd = head * 64 + nt * 8 + 2 * tg;
            float2 v0 = {o[mt][nt][0] * i0, o[mt][nt][1] * i0};
            float2 v1 = {o[mt][nt][2] * i1, o[mt][nt][3] * i1};
            *reinterpret_cast<float2*>(&out[((size_t)b * S_ + r0) * H_ + dd]) = v0;
            *reinterpret_cast<float2*>(&out[((size_t)b * S_ + r1) * H_ + dd]) = v1;
        }
    }
}

// ---------------------------------------------------------------------------
extern "C" void kernel_launch(void* const* d_in, const int* in_sizes, int n_in,
                              void* d_out, int out_size)
{
    const float* hs   = (const float*)d_in[0];
    const float* mask = (const float*)d_in[1];
    const float* Wq   = (const float*)d_in[2];
    const float* bq   = (const float*)d_in[3];
    const float* Wk   = (const float*)d_in[4];
    const float* bk   = (const float*)d_in[5];
    const float* Wv   = (const float*)d_in[6];
    const float* bv   = (const float*)d_in[7];
    float* out = (float*)d_out;

    cudaFuncSetAttribute(attention, cudaFuncAttributeMaxDynamicSharedMemorySize, 78848);

    dim3 ggemm(H_ / 128, (B_ * S_) / 128, 3);   // (8, 32, 3) — fused Q/K/V
    qkv_gemm<<<ggemm, 256>>>(hs, Wq, Wk, Wv, bq, bk, bv);

    dim3 gattn(S_ / 128, NH_, B_);              // (16, 16, 2)
    attention<<<gattn, 128, 78848>>>(mask, out);
}

// round 4
// speedup vs baseline: 5.4236x; 1.3423x over previous
#include <cuda_runtime.h>
#include <cuda_bf16.h>
#include <cuda_fp16.h>
#include <cstdint>

#define B_   2
#define S_   2048
#define H_   1024
#define NH_  16
#define D_   64

// Scratch Q/K/V in head-major layout [b, h, s, d], fp32 (16 MB each)
__device__ __align__(16) float g_Q[B_ * NH_ * S_ * D_];
__device__ __align__(16) float g_K[B_ * NH_ * S_ * D_];
__device__ __align__(16) float g_V[B_ * NH_ * S_ * D_];

// pack two fp32 -> half2 (lo = first arg)
__device__ __forceinline__ uint32_t packh2(float lo, float hi) {
    uint32_t r;
    asm("cvt.rn.f16x2.f32 %0, %1, %2;" : "=r"(r) : "f"(hi), "f"(lo));
    return r;
}

__device__ __forceinline__ void mma_f16(float c[4], const uint32_t a[4],
                                        uint32_t b0, uint32_t b1) {
    asm volatile(
        "mma.sync.aligned.m16n8k16.row.col.f32.f16.f16.f32 "
        "{%0,%1,%2,%3}, {%4,%5,%6,%7}, {%8,%9}, {%0,%1,%2,%3};\n"
        : "+f"(c[0]), "+f"(c[1]), "+f"(c[2]), "+f"(c[3])
        : "r"(a[0]), "r"(a[1]), "r"(a[2]), "r"(a[3]), "r"(b0), "r"(b1));
}

// ---------------------------------------------------------------------------
// Fused QKV projection (fp16 mma, fp32 accumulate). Block tile 128x128,
// K-chunk 32 (2 x k16). 256 threads = 8 warps (4M x 2N), warp tile 32x64.
// ---------------------------------------------------------------------------
__global__ __launch_bounds__(256) void qkv_gemm(
    const float* __restrict__ X,
    const float* __restrict__ Wq, const float* __restrict__ Wk,
    const float* __restrict__ Wv,
    const float* __restrict__ bq, const float* __restrict__ bk,
    const float* __restrict__ bv)
{
    __shared__ uint32_t As[128][20];   // [m][k-pair], (20g+tg)%32 distinct
    __shared__ uint32_t Bs[16][132];   // [k-pair][n], (4tg+g)%32 distinct

    const float* W; const float* bias; float* out;
    if (blockIdx.z == 0)      { W = Wq; bias = bq; out = g_Q; }
    else if (blockIdx.z == 1) { W = Wk; bias = bk; out = g_K; }
    else                      { W = Wv; bias = bv; out = g_V; }

    const int tid   = threadIdx.x;
    const int wid   = tid >> 5;
    const int lane  = tid & 31;
    const int g     = lane >> 2;
    const int tg    = lane & 3;
    const int warpM = wid >> 1;
    const int warpN = wid & 1;
    const int row0  = blockIdx.y * 128;
    const int col0  = blockIdx.x * 128;

    float c[2][8][4];
#pragma unroll
    for (int mt = 0; mt < 2; mt++)
#pragma unroll
        for (int nt = 0; nt < 8; nt++)
#pragma unroll
            for (int j = 0; j < 4; j++) c[mt][nt][j] = 0.f;

    for (int k0 = 0; k0 < H_; k0 += 32) {
        // A tile 128x32 -> packed [128][16]
#pragma unroll
        for (int p = 0; p < 2; p++) {
            int r  = p * 64 + (tid >> 2);
            int kc = (tid & 3) * 8;
            float4 v0 = *reinterpret_cast<const float4*>(&X[(size_t)(row0 + r) * H_ + k0 + kc]);
            float4 v1 = *reinterpret_cast<const float4*>(&X[(size_t)(row0 + r) * H_ + k0 + kc + 4]);
            uint4 u = {packh2(v0.x, v0.y), packh2(v0.z, v0.w),
                       packh2(v1.x, v1.y), packh2(v1.z, v1.w)};
            *reinterpret_cast<uint4*>(&As[r][kc >> 1]) = u;
        }
        // B tile 32x128 -> pair-packed [16][128]
#pragma unroll
        for (int p = 0; p < 2; p++) {
            int pr = p * 8 + (tid >> 5);
            int n  = (tid & 31) * 4;
            float4 v0 = *reinterpret_cast<const float4*>(&W[(size_t)(k0 + 2 * pr) * H_ + col0 + n]);
            float4 v1 = *reinterpret_cast<const float4*>(&W[(size_t)(k0 + 2 * pr + 1) * H_ + col0 + n]);
            uint4 u = {packh2(v0.x, v1.x), packh2(v0.y, v1.y),
                       packh2(v0.z, v1.z), packh2(v0.w, v1.w)};
            *reinterpret_cast<uint4*>(&Bs[pr][n]) = u;
        }
        __syncthreads();

#pragma unroll
        for (int kk = 0; kk < 2; kk++) {
            uint32_t a[2][4], b[8][2];
#pragma unroll
            for (int mt = 0; mt < 2; mt++) {
                int rb = warpM * 32 + mt * 16;
                a[mt][0] = As[rb + g][kk * 8 + tg];
                a[mt][1] = As[rb + g + 8][kk * 8 + tg];
                a[mt][2] = As[rb + g][kk * 8 + tg + 4];
                a[mt][3] = As[rb + g + 8][kk * 8 + tg + 4];
            }
#pragma unroll
            for (int nt = 0; nt < 8; nt++) {
                int nb = warpN * 64 + nt * 8;
                b[nt][0] = Bs[kk * 8 + tg][nb + g];
                b[nt][1] = Bs[kk * 8 + tg + 4][nb + g];
            }
#pragma unroll
            for (int mt = 0; mt < 2; mt++)
#pragma unroll
                for (int nt = 0; nt < 8; nt++)
                    mma_f16(c[mt][nt], a[mt], b[nt][0], b[nt][1]);
        }
        __syncthreads();
    }

    const int head = ((col0 + warpN * 64) >> 6);
#pragma unroll
    for (int mt = 0; mt < 2; mt++) {
#pragma unroll
        for (int nt = 0; nt < 8; nt++) {
            int dd   = nt * 8 + 2 * tg;
            int coln = col0 + warpN * 64 + dd;
            float b0 = bias[coln], b1 = bias[coln + 1];
            int r0 = row0 + warpM * 32 + mt * 16 + g;
            int r1 = r0 + 8;
            int bb0 = r0 >> 11, s0 = r0 & 2047;
            int bb1 = r1 >> 11, s1 = r1 & 2047;
            float2 v0 = {c[mt][nt][0] + b0, c[mt][nt][1] + b1};
            float2 v1 = {c[mt][nt][2] + b0, c[mt][nt][3] + b1};
            *reinterpret_cast<float2*>(
                &out[(((size_t)(bb0 * NH_ + head) * S_ + s0) * D_) + dd]) = v0;
            *reinterpret_cast<float2*>(
                &out[(((size_t)(bb1 * NH_ + head) * S_ + s1) * D_) + dd]) = v1;
        }
    }
}

// ---------------------------------------------------------------------------
// Flash attention, fp16 mma (fp32 softmax/accum). 128 q-rows per block,
// 4 warps x 32 rows. P never leaves registers: score C-frags pack directly
// into PV A-frags (m16n8k16 layout identity). Zero shuffles.
// ---------------------------------------------------------------------------
__global__ __launch_bounds__(128) void attention(
    const float* __restrict__ mask, float* __restrict__ out)
{
    __shared__ uint32_t Qp[128][36];   // q-row major, d-pairs
    __shared__ uint32_t Kp[64][36];    // key-row major, d-pairs
    __shared__ uint32_t Vp[32][68];    // key-PAIR major: {V[2p][d],V[2p+1][d]}
    __shared__ float    msk[S_];

    const int tid  = threadIdx.x;
    const int w    = tid >> 5;
    const int lane = tid & 31;
    const int g    = lane >> 2;
    const int tg   = lane & 3;
    const int rb   = w * 32;
    const int qt   = blockIdx.x;
    const int head = blockIdx.y;
    const int b    = blockIdx.z;

    const float* Qg = g_Q + ((size_t)(b * NH_ + head) * S_ + qt * 128) * D_;
    const float* Kg = g_K + (size_t)(b * NH_ + head) * S_ * D_;
    const float* Vg = g_V + (size_t)(b * NH_ + head) * S_ * D_;

    // Stage Q tile (fp16-packed)
#pragma unroll
    for (int p = 0; p < 16; p++) {
        int r = p * 8 + (tid >> 4);
        int c = (tid & 15) * 4;
        float4 v = *reinterpret_cast<const float4*>(&Qg[(size_t)r * 64 + c]);
        uint2 u = {packh2(v.x, v.y), packh2(v.z, v.w)};
        *reinterpret_cast<uint2*>(&Qp[r][c >> 1]) = u;
    }
    for (int i = tid; i < S_; i += 128) msk[i] = mask[(size_t)b * S_ + i];

    float o[2][8][4];
#pragma unroll
    for (int mt = 0; mt < 2; mt++)
#pragma unroll
        for (int nt = 0; nt < 8; nt++)
#pragma unroll
            for (int j = 0; j < 4; j++) o[mt][nt][j] = 0.f;
    float mx[2][2] = {{-1e30f, -1e30f}, {-1e30f, -1e30f}};
    float l[2][2]  = {{0.f, 0.f}, {0.f, 0.f}};

    for (int t = 0; t < 32; t++) {
        __syncthreads();   // prior tile done with Kp/Vp (covers Q/msk at t=0)

        // Stage K (row-major pairs) and V (key-pair-major)
#pragma unroll
        for (int p = 0; p < 8; p++) {
            int r = p * 8 + (tid >> 4);
            int c = (tid & 15) * 4;
            float4 kv = *reinterpret_cast<const float4*>(&Kg[(size_t)(t * 64 + r) * 64 + c]);
            uint2 ku = {packh2(kv.x, kv.y), packh2(kv.z, kv.w)};
            *reinterpret_cast<uint2*>(&Kp[r][c >> 1]) = ku;
        }
#pragma unroll
        for (int p = 0; p < 4; p++) {
            int pr = p * 8 + (tid >> 4);
            int c  = (tid & 15) * 4;
            float4 v0 = *reinterpret_cast<const float4*>(&Vg[(size_t)(t * 64 + 2 * pr) * 64 + c]);
            float4 v1 = *reinterpret_cast<const float4*>(&Vg[(size_t)(t * 64 + 2 * pr + 1) * 64 + c]);
            uint4 u = {packh2(v0.x, v1.x), packh2(v0.y, v1.y),
                       packh2(v0.z, v1.z), packh2(v0.w, v1.w)};
            *reinterpret_cast<uint4*>(&Vp[pr][c]) = u;
        }
        __syncthreads();

        // ---- Scores: S = Q @ K^T (32 rows x 64 key cols, 4 k16 steps)
        float s[2][8][4];
#pragma unroll
        for (int mt = 0; mt < 2; mt++)
#pragma unroll
            for (int nt = 0; nt < 8; nt++)
#pragma unroll
                for (int j = 0; j < 4; j++) s[mt][nt][j] = 0.f;

#pragma unroll
        for (int kk = 0; kk < 4; kk++) {
            uint32_t a[2][4];
#pragma unroll
            for (int mt = 0; mt < 2; mt++) {
                int r = rb + mt * 16;
                a[mt][0] = Qp[r + g][kk * 8 + tg];
                a[mt][1] = Qp[r + g + 8][kk * 8 + tg];
                a[mt][2] = Qp[r + g][kk * 8 + tg + 4];
                a[mt][3] = Qp[r + g + 8][kk * 8 + tg + 4];
            }
#pragma unroll
            for (int nt = 0; nt < 8; nt++) {
                uint32_t b0 = Kp[nt * 8 + g][kk * 8 + tg];
                uint32_t b1 = Kp[nt * 8 + g][kk * 8 + tg + 4];
                mma_f16(s[0][nt], a[0], b0, b1);
                mma_f16(s[1][nt], a[1], b0, b1);
            }
        }

        float mk[8][2];
#pragma unroll
        for (int nt = 0; nt < 8; nt++) {
            float2 mv = *reinterpret_cast<const float2*>(&msk[t * 64 + nt * 8 + 2 * tg]);
            mk[nt][0] = mv.x; mk[nt][1] = mv.y;
        }

        // ---- Online softmax per m-tile
#pragma unroll
        for (int mt = 0; mt < 2; mt++) {
            float rm0 = -1e30f, rm1 = -1e30f;
#pragma unroll
            for (int nt = 0; nt < 8; nt++) {
                s[mt][nt][0] = s[mt][nt][0] * 0.125f + mk[nt][0];
                s[mt][nt][1] = s[mt][nt][1] * 0.125f + mk[nt][1];
                s[mt][nt][2] = s[mt][nt][2] * 0.125f + mk[nt][0];
                s[mt][nt][3] = s[mt][nt][3] * 0.125f + mk[nt][1];
                rm0 = fmaxf(rm0, fmaxf(s[mt][nt][0], s[mt][nt][1]));
                rm1 = fmaxf(rm1, fmaxf(s[mt][nt][2], s[mt][nt][3]));
            }
            rm0 = fmaxf(rm0, __shfl_xor_sync(0xffffffffu, rm0, 1));
            rm0 = fmaxf(rm0, __shfl_xor_sync(0xffffffffu, rm0, 2));
            rm1 = fmaxf(rm1, __shfl_xor_sync(0xffffffffu, rm1, 1));
            rm1 = fmaxf(rm1, __shfl_xor_sync(0xffffffffu, rm1, 2));
            float mn0 = fmaxf(mx[mt][0], rm0), mn1 = fmaxf(mx[mt][1], rm1);
            float al0 = __expf(mx[mt][0] - mn0), al1 = __expf(mx[mt][1] - mn1);
            mx[mt][0] = mn0; mx[mt][1] = mn1;
            float rs0 = 0.f, rs1 = 0.f;
#pragma unroll
            for (int nt = 0; nt < 8; nt++) {
                s[mt][nt][0] = __expf(s[mt][nt][0] - mn0);
                s[mt][nt][1] = __expf(s[mt][nt][1] - mn0);
                s[mt][nt][2] = __expf(s[mt][nt][2] - mn1);
                s[mt][nt][3] = __expf(s[mt][nt][3] - mn1);
                rs0 += s[mt][nt][0] + s[mt][nt][1];
                rs1 += s[mt][nt][2] + s[mt][nt][3];
            }
            rs0 += __shfl_xor_sync(0xffffffffu, rs0, 1);
            rs0 += __shfl_xor_sync(0xffffffffu, rs0, 2);
            rs1 += __shfl_xor_sync(0xffffffffu, rs1, 1);
            rs1 += __shfl_xor_sync(0xffffffffu, rs1, 2);
            l[mt][0] = l[mt][0] * al0 + rs0;
            l[mt][1] = l[mt][1] * al1 + rs1;
#pragma unroll
            for (int nt = 0; nt < 8; nt++) {
                o[mt][nt][0] *= al0; o[mt][nt][1] *= al0;
                o[mt][nt][2] *= al1; o[mt][nt][3] *= al1;
            }
        }

        // ---- O += P @ V : C-frag packs straight into A-frag, no shuffles
#pragma unroll
        for (int kk = 0; kk < 4; kk++) {
            uint32_t ap[2][4];
#pragma unroll
            for (int mt = 0; mt < 2; mt++) {
                ap[mt][0] = packh2(s[mt][2 * kk][0],     s[mt][2 * kk][1]);
                ap[mt][1] = packh2(s[mt][2 * kk][2],     s[mt][2 * kk][3]);
                ap[mt][2] = packh2(s[mt][2 * kk + 1][0], s[mt][2 * kk + 1][1]);
                ap[mt][3] = packh2(s[mt][2 * kk + 1][2], s[mt][2 * kk + 1][3]);
            }
#pragma unroll
            for (int nt = 0; nt < 8; nt++) {
                uint32_t b0 = Vp[kk * 8 + tg][nt * 8 + g];
                uint32_t b1 = Vp[kk * 8 + tg + 4][nt * 8 + g];
                mma_f16(o[0][nt], ap[0], b0, b1);
                mma_f16(o[1][nt], ap[1], b0, b1);
            }
        }
    }

    // ---- Epilogue
#pragma unroll
    for (int mt = 0; mt < 2; mt++) {
        float i0 = 1.0f / l[mt][0], i1 = 1.0f / l[mt][1];
        int r0 = qt * 128 + rb + mt * 16 + g;
        int r1 = r0 + 8;
#pragma unroll
        for (int nt = 0; nt < 8; nt++) {
            int dd = head * 64 + nt * 8 + 2 * tg;
            float2 v0 = {o[mt][nt][0] * i0, o[mt][nt][1] * i0};
            float2 v1 = {o[mt][nt][2] * i1, o[mt][nt][3] * i1};
            *reinterpret_cast<float2*>(&out[((size_t)b * S_ + r0) * H_ + dd]) = v0;
            *reinterpret_cast<float2*>(&out[((size_t)b * S_ + r1) * H_ + dd]) = v1;
        }
    }
}

// ---------------------------------------------------------------------------
extern "C" void kernel_launch(void* const* d_in, const int* in_sizes, int n_in,
                              void* d_out, int out_size)
{
    const float* hs   = (const float*)d_in[0];
    const float* mask = (const float*)d_in[1];
    const float* Wq   = (const float*)d_in[2];
    const float* bq   = (const float*)d_in[3];
    const float* Wk   = (const float*)d_in[4];
    const float* bk   = (const float*)d_in[5];
    const float* Wv   = (const float*)d_in[6];
    const float* bv   = (const float*)d_in[7];
    float* out = (float*)d_out;

    dim3 ggemm(H_ / 128, (B_ * S_) / 128, 3);   // fused Q/K/V
    qkv_gemm<<<ggemm, 256>>>(hs, Wq, Wk, Wv, bq, bk, bv);

    dim3 gattn(S_ / 128, NH_, B_);              // (16, 16, 2)
    attention<<<gattn, 128>>>(mask, out);
}

// round 5
// speedup vs baseline: 6.8142x; 1.2564x over previous
#include <cuda_runtime.h>
#include <cuda_bf16.h>
#include <cuda_fp16.h>
#include <cstdint>

#define B_   2
#define S_   2048
#define H_   1024
#define NH_  16
#define D_   64

// fp16 operand / result arrays (word = packed half2)
__device__ __align__(16) uint32_t g_Xw[4096 * 512];            // X row-major k-pairs
__device__ __align__(16) uint32_t g_Ww[3 * 512 * 1024];        // W k-pair interleaved
__device__ __align__(16) uint32_t g_QKw[2][B_ * NH_ * S_ * 32]; // Q,K head-major d-pairs
__device__ __align__(16) __half   g_Vh[B_ * NH_ * S_ * D_];     // V key-pair interleaved

// pack two fp32 -> half2 (lo = first arg)
__device__ __forceinline__ uint32_t packh2(float lo, float hi) {
    uint32_t r;
    asm("cvt.rn.f16x2.f32 %0, %1, %2;" : "=r"(r) : "f"(hi), "f"(lo));
    return r;
}

__device__ __forceinline__ void mma_f16(float c[4], const uint32_t a[4],
                                        uint32_t b0, uint32_t b1) {
    asm volatile(
        "mma.sync.aligned.m16n8k16.row.col.f32.f16.f16.f32 "
        "{%0,%1,%2,%3}, {%4,%5,%6,%7}, {%8,%9}, {%0,%1,%2,%3};\n"
        : "+f"(c[0]), "+f"(c[1]), "+f"(c[2]), "+f"(c[3])
        : "r"(a[0]), "r"(a[1]), "r"(a[2]), "r"(a[3]), "r"(b0), "r"(b1));
}

__device__ __forceinline__ void cpa16(uint32_t dst, const void* src) {
    asm volatile("cp.async.cg.shared.global [%0], [%1], 16;\n" :: "r"(dst), "l"(src));
}
#define CP_COMMIT() asm volatile("cp.async.commit_group;\n" ::: "memory")
#define CP_WAIT1()  asm volatile("cp.async.wait_group 1;\n" ::: "memory")

// ---------------------------------------------------------------------------
// Converters (one-time): fp32 -> fp16 packed layouts
// ---------------------------------------------------------------------------
__global__ __launch_bounds__(256) void cvtX(const float* __restrict__ X) {
    int idx = blockIdx.x * 256 + threadIdx.x;           // 0 .. 1048575
    float4 v = *reinterpret_cast<const float4*>(&X[(size_t)idx * 4]);
    uint2 u = {packh2(v.x, v.y), packh2(v.z, v.w)};
    *reinterpret_cast<uint2*>(&g_Xw[(size_t)idx * 2]) = u;
}

__global__ __launch_bounds__(256) void cvtW(
    const float* __restrict__ Wq, const float* __restrict__ Wk,
    const float* __restrict__ Wv)
{
    const float* W = (blockIdx.z == 0) ? Wq : (blockIdx.z == 1) ? Wk : Wv;
    int idx = blockIdx.x * 256 + threadIdx.x;           // 0 .. 131071
    int p = idx >> 8;                                    // k-pair 0..511
    int n = (idx & 255) * 4;
    float4 a = *reinterpret_cast<const float4*>(&W[(size_t)(2 * p) * H_ + n]);
    float4 b = *reinterpret_cast<const float4*>(&W[(size_t)(2 * p + 1) * H_ + n]);
    uint4 u = {packh2(a.x, b.x), packh2(a.y, b.y), packh2(a.z, b.z), packh2(a.w, b.w)};
    *reinterpret_cast<uint4*>(&g_Ww[(size_t)blockIdx.z * 524288 + p * 1024 + n]) = u;
}

// ---------------------------------------------------------------------------
// Fused QKV GEMM, fp16 operands via cp.async double-buffer. Block 128x128,
// k-chunk 32 (2 x k16). 256 thr = 8 warps (4M x 2N), warp tile 32x64.
// ---------------------------------------------------------------------------
__global__ __launch_bounds__(256) void qkv_gemm(
    const float* __restrict__ bq, const float* __restrict__ bk,
    const float* __restrict__ bv)
{
    __shared__ uint32_t As[2][128][20];   // [m][k-pair], (4g+tg)%32 distinct
    __shared__ uint32_t Bs[2][16][132];   // [k-pair][n], (4tg+g)%32 distinct

    const int z = blockIdx.z;
    const float* bias = (z == 0) ? bq : (z == 1) ? bk : bv;

    const int tid   = threadIdx.x;
    const int wid   = tid >> 5;
    const int lane  = tid & 31;
    const int g     = lane >> 2;
    const int tg    = lane & 3;
    const int warpM = wid >> 1;
    const int warpN = wid & 1;
    const int row0  = blockIdx.y * 128;
    const int col0  = blockIdx.x * 128;

    const uint32_t AO = (uint32_t)__cvta_generic_to_shared(&As[0][0][0]);
    const uint32_t BO = (uint32_t)__cvta_generic_to_shared(&Bs[0][0][0]);
    const uint32_t* Wz = g_Ww + (size_t)z * 524288 + col0;

    float c[2][8][4];
#pragma unroll
    for (int mt = 0; mt < 2; mt++)
#pragma unroll
        for (int nt = 0; nt < 8; nt++)
#pragma unroll
            for (int j = 0; j < 4; j++) c[mt][nt][j] = 0.f;

    // stage k-chunk kc into buffer buf
    auto stage = [&](int kc, int buf) {
#pragma unroll
        for (int p = 0; p < 2; p++) {
            int cid = p * 256 + tid;
            int r = cid >> 2, ch = cid & 3;
            cpa16(AO + (uint32_t)(buf * 10240 + r * 80 + ch * 16),
                  g_Xw + (size_t)(row0 + r) * 512 + kc * 16 + ch * 4);
        }
#pragma unroll
        for (int p = 0; p < 2; p++) {
            int cid = p * 256 + tid;
            int pr = cid >> 5, ch = cid & 31;
            cpa16(BO + (uint32_t)(buf * 8448 + pr * 528 + ch * 16),
                  Wz + (size_t)(kc * 16 + pr) * 1024 + ch * 4);
        }
    };

    stage(0, 0);
    CP_COMMIT();

    for (int kc = 0; kc < 32; kc++) {
        __syncthreads();                    // all warps done with buf (kc+1)&1
        if (kc + 1 < 32) stage(kc + 1, (kc + 1) & 1);
        CP_COMMIT();
        CP_WAIT1();                         // chunk kc ready
        __syncthreads();
        const int buf = kc & 1;

#pragma unroll
        for (int kk = 0; kk < 2; kk++) {
            uint32_t a[2][4], b[8][2];
#pragma unroll
            for (int mt = 0; mt < 2; mt++) {
                int rb = warpM * 32 + mt * 16;
                a[mt][0] = As[buf][rb + g][kk * 8 + tg];
                a[mt][1] = As[buf][rb + g + 8][kk * 8 + tg];
                a[mt][2] = As[buf][rb + g][kk * 8 + tg + 4];
                a[mt][3] = As[buf][rb + g + 8][kk * 8 + tg + 4];
            }
#pragma unroll
            for (int nt = 0; nt < 8; nt++) {
                int nb = warpN * 64 + nt * 8;
                b[nt][0] = Bs[buf][kk * 8 + tg][nb + g];
                b[nt][1] = Bs[buf][kk * 8 + tg + 4][nb + g];
            }
#pragma unroll
            for (int mt = 0; mt < 2; mt++)
#pragma unroll
                for (int nt = 0; nt < 8; nt++)
                    mma_f16(c[mt][nt], a[mt], b[nt][0], b[nt][1]);
        }
    }

    // Epilogue: bias add fp32, write fp16 in attention-ready layouts
    const int head = ((col0 + warpN * 64) >> 6);
#pragma unroll
    for (int mt = 0; mt < 2; mt++) {
#pragma unroll
        for (int nt = 0; nt < 8; nt++) {
            int dd   = nt * 8 + 2 * tg;
            int coln = col0 + warpN * 64 + dd;
            float b0 = bias[coln], b1 = bias[coln + 1];
            int r0 = row0 + warpM * 32 + mt * 16 + g;
            int r1 = r0 + 8;
            float v00 = c[mt][nt][0] + b0, v01 = c[mt][nt][1] + b1;
            float v10 = c[mt][nt][2] + b0, v11 = c[mt][nt][3] + b1;
            if (z < 2) {
                int bb0 = r0 >> 11, s0 = r0 & 2047;
                int bb1 = r1 >> 11, s1 = r1 & 2047;
                g_QKw[z][((size_t)(bb0 * NH_ + head) * S_ + s0) * 32 + (dd >> 1)] =
                    packh2(v00, v01);
                g_QKw[z][((size_t)(bb1 * NH_ + head) * S_ + s1) * 32 + (dd >> 1)] =
                    packh2(v10, v11);
            } else {
                int bb0 = r0 >> 11, s0 = r0 & 2047;
                int bb1 = r1 >> 11, s1 = r1 & 2047;
                size_t base0 = (size_t)(bb0 * NH_ + head) * 131072 + (s0 >> 1) * 128 + (s0 & 1);
                size_t base1 = (size_t)(bb1 * NH_ + head) * 131072 + (s1 >> 1) * 128 + (s1 & 1);
                g_Vh[base0 + dd * 2]       = __float2half_rn(v00);
                g_Vh[base0 + (dd + 1) * 2] = __float2half_rn(v01);
                g_Vh[base1 + dd * 2]       = __float2half_rn(v10);
                g_Vh[base1 + (dd + 1) * 2] = __float2half_rn(v11);
            }
        }
    }
}

// ---------------------------------------------------------------------------
// Flash attention, fp16 mma, cp.async double-buffered K/V. 128 q-rows/block,
// 4 warps x 32 rows. P stays in registers (C-frag -> A-frag pack identity).
// ---------------------------------------------------------------------------
__global__ __launch_bounds__(128) void attention(
    const float* __restrict__ mask, float* __restrict__ out)
{
    extern __shared__ uint32_t smu[];
    uint32_t* Qp = smu;                          // [128][36]
    uint32_t* Kp = smu + 4608;                   // [2][64][36]
    uint32_t* Vp = smu + 9216;                   // [2][32][68]
    float*    msk = (float*)(smu + 13568);       // [2048]

    const int tid  = threadIdx.x;
    const int w    = tid >> 5;
    const int lane = tid & 31;
    const int g    = lane >> 2;
    const int tg   = lane & 3;
    const int rb   = w * 32;
    const int qt   = blockIdx.x;
    const int head = blockIdx.y;
    const int b    = blockIdx.z;
    const int bh   = b * NH_ + head;

    const uint32_t smb = (uint32_t)__cvta_generic_to_shared(smu);
    const uint32_t QO = smb;
    const uint32_t KO = smb + 4608 * 4;
    const uint32_t VO = smb + 9216 * 4;

    const uint32_t* Qsrc = g_QKw[0] + ((size_t)bh * S_ + qt * 128) * 32;
    const uint32_t* Ksrc = g_QKw[1] + (size_t)bh * S_ * 32;
    const __half*   Vsrc = g_Vh + (size_t)bh * 131072;

    auto stageKV = [&](int t, int buf) {
#pragma unroll
        for (int p = 0; p < 4; p++) {
            int cid = p * 128 + tid;
            int r = cid >> 3, ch = cid & 7;
            cpa16(KO + (uint32_t)(buf * 9216 + r * 144 + ch * 16),
                  Ksrc + (size_t)(t * 64 + r) * 32 + ch * 4);
        }
#pragma unroll
        for (int p = 0; p < 4; p++) {
            int cid = p * 128 + tid;
            int pr = cid >> 4, ch = cid & 15;
            cpa16(VO + (uint32_t)(buf * 8704 + pr * 272 + ch * 16),
                  Vsrc + (size_t)(t * 32 + pr) * 128 + ch * 8);
        }
    };

    // Prologue: Q + tile 0 in group 0, mask via plain loads
#pragma unroll
    for (int p = 0; p < 8; p++) {
        int cid = p * 128 + tid;
        int r = cid >> 3, ch = cid & 7;
        cpa16(QO + (uint32_t)(r * 144 + ch * 16), Qsrc + (size_t)r * 32 + ch * 4);
    }
    stageKV(0, 0);
    CP_COMMIT();
    for (int i = tid; i < S_; i += 128) msk[i] = mask[(size_t)b * S_ + i];

    float o[2][8][4];
#pragma unroll
    for (int mt = 0; mt < 2; mt++)
#pragma unroll
        for (int nt = 0; nt < 8; nt++)
#pragma unroll
            for (int j = 0; j < 4; j++) o[mt][nt][j] = 0.f;
    float mx[2][2] = {{-1e30f, -1e30f}, {-1e30f, -1e30f}};
    float l[2][2]  = {{0.f, 0.f}, {0.f, 0.f}};

    for (int t = 0; t < 32; t++) {
        __syncthreads();                 // all warps done computing t-1
        if (t + 1 < 32) stageKV(t + 1, (t + 1) & 1);
        CP_COMMIT();
        CP_WAIT1();                      // tile t arrived
        __syncthreads();

        const uint32_t* Kb = Kp + (t & 1) * 2304;
        const uint32_t* Vb = Vp + (t & 1) * 2176;

        // ---- Scores: S = Q @ K^T (32 rows x 64 key cols, 4 k16 steps)
        float s[2][8][4];
#pragma unroll
        for (int mt = 0; mt < 2; mt++)
#pragma unroll
            for (int nt = 0; nt < 8; nt++)
#pragma unroll
                for (int j = 0; j < 4; j++) s[mt][nt][j] = 0.f;

#pragma unroll
        for (int kk = 0; kk < 4; kk++) {
            uint32_t a[2][4];
#pragma unroll
            for (int mt = 0; mt < 2; mt++) {
                int r = rb + mt * 16;
                a[mt][0] = Qp[(r + g) * 36 + kk * 8 + tg];
                a[mt][1] = Qp[(r + g + 8) * 36 + kk * 8 + tg];
                a[mt][2] = Qp[(r + g) * 36 + kk * 8 + tg + 4];
                a[mt][3] = Qp[(r + g + 8) * 36 + kk * 8 + tg + 4];
            }
#pragma unroll
            for (int nt = 0; nt < 8; nt++) {
                uint32_t b0 = Kb[(nt * 8 + g) * 36 + kk * 8 + tg];
                uint32_t b1 = Kb[(nt * 8 + g) * 36 + kk * 8 + tg + 4];
                mma_f16(s[0][nt], a[0], b0, b1);
                mma_f16(s[1][nt], a[1], b0, b1);
            }
        }

        float mk[8][2];
#pragma unroll
        for (int nt = 0; nt < 8; nt++) {
            float2 mv = *reinterpret_cast<const float2*>(&msk[t * 64 + nt * 8 + 2 * tg]);
            mk[nt][0] = mv.x; mk[nt][1] = mv.y;
        }

        // ---- Online softmax per m-tile
#pragma unroll
        for (int mt = 0; mt < 2; mt++) {
            float rm0 = -1e30f, rm1 = -1e30f;
#pragma unroll
            for (int nt = 0; nt < 8; nt++) {
                s[mt][nt][0] = s[mt][nt][0] * 0.125f + mk[nt][0];
                s[mt][nt][1] = s[mt][nt][1] * 0.125f + mk[nt][1];
                s[mt][nt][2] = s[mt][nt][2] * 0.125f + mk[nt][0];
                s[mt][nt][3] = s[mt][nt][3] * 0.125f + mk[nt][1];
                rm0 = fmaxf(rm0, fmaxf(s[mt][nt][0], s[mt][nt][1]));
                rm1 = fmaxf(rm1, fmaxf(s[mt][nt][2], s[mt][nt][3]));
            }
            rm0 = fmaxf(rm0, __shfl_xor_sync(0xffffffffu, rm0, 1));
            rm0 = fmaxf(rm0, __shfl_xor_sync(0xffffffffu, rm0, 2));
            rm1 = fmaxf(rm1, __shfl_xor_sync(0xffffffffu, rm1, 1));
            rm1 = fmaxf(rm1, __shfl_xor_sync(0xffffffffu, rm1, 2));
            float mn0 = fmaxf(mx[mt][0], rm0), mn1 = fmaxf(mx[mt][1], rm1);
            float al0 = __expf(mx[mt][0] - mn0), al1 = __expf(mx[mt][1] - mn1);
            mx[mt][0] = mn0; mx[mt][1] = mn1;
            float rs0 = 0.f, rs1 = 0.f;
#pragma unroll
            for (int nt = 0; nt < 8; nt++) {
                s[mt][nt][0] = __expf(s[mt][nt][0] - mn0);
                s[mt][nt][1] = __expf(s[mt][nt][1] - mn0);
                s[mt][nt][2] = __expf(s[mt][nt][2] - mn1);
                s[mt][nt][3] = __expf(s[mt][nt][3] - mn1);
                rs0 += s[mt][nt][0] + s[mt][nt][1];
                rs1 += s[mt][nt][2] + s[mt][nt][3];
            }
            rs0 += __shfl_xor_sync(0xffffffffu, rs0, 1);
            rs0 += __shfl_xor_sync(0xffffffffu, rs0, 2);
            rs1 += __shfl_xor_sync(0xffffffffu, rs1, 1);
            rs1 += __shfl_xor_sync(0xffffffffu, rs1, 2);
            l[mt][0] = l[mt][0] * al0 + rs0;
            l[mt][1] = l[mt][1] * al1 + rs1;
#pragma unroll
            for (int nt = 0; nt < 8; nt++) {
                o[mt][nt][0] *= al0; o[mt][nt][1] *= al0;
                o[mt][nt][2] *= al1; o[mt][nt][3] *= al1;
            }
        }

        // ---- O += P @ V : C-frag packs straight into A-frag
#pragma unroll
        for (int kk = 0; kk < 4; kk++) {
            uint32_t ap[2][4];
#pragma unroll
            for (int mt = 0; mt < 2; mt++) {
                ap[mt][0] = packh2(s[mt][2 * kk][0],     s[mt][2 * kk][1]);
                ap[mt][1] = packh2(s[mt][2 * kk][2],     s[mt][2 * kk][3]);
                ap[mt][2] = packh2(s[mt][2 * kk + 1][0], s[mt][2 * kk + 1][1]);
                ap[mt][3] = packh2(s[mt][2 * kk + 1][2], s[mt][2 * kk + 1][3]);
            }
#pragma unroll
            for (int nt = 0; nt < 8; nt++) {
                uint32_t b0 = Vb[(kk * 8 + tg) * 68 + nt * 8 + g];
                uint32_t b1 = Vb[(kk * 8 + tg + 4) * 68 + nt * 8 + g];
                mma_f16(o[0][nt], ap[0], b0, b1);
                mma_f16(o[1][nt], ap[1], b0, b1);
            }
        }
    }

    // ---- Epilogue
#pragma unroll
    for (int mt = 0; mt < 2; mt++) {
        float i0 = 1.0f / l[mt][0], i1 = 1.0f / l[mt][1];
        int r0 = qt * 128 + rb + mt * 16 + g;
        int r1 = r0 + 8;
#pragma unroll
        for (int nt = 0; nt < 8; nt++) {
            int dd = head * 64 + nt * 8 + 2 * tg;
            float2 v0 = {o[mt][nt][0] * i0, o[mt][nt][1] * i0};
            float2 v1 = {o[mt][nt][2] * i1, o[mt][nt][3] * i1};
            *reinterpret_cast<float2*>(&out[((size_t)b * S_ + r0) * H_ + dd]) = v0;
            *reinterpret_cast<float2*>(&out[((size_t)b * S_ + r1) * H_ + dd]) = v1;
        }
    }
}

// ---------------------------------------------------------------------------
extern "C" void kernel_launch(void* const* d_in, const int* in_sizes, int n_in,
                              void* d_out, int out_size)
{
    const float* hs   = (const float*)d_in[0];
    const float* mask = (const float*)d_in[1];
    const float* Wq   = (const float*)d_in[2];
    const float* bq   = (const float*)d_in[3];
    const float* Wk   = (const float*)d_in[4];
    const float* bk   = (const float*)d_in[5];
    const float* Wv   = (const float*)d_in[6];
    const float* bv   = (const float*)d_in[7];
    float* out = (float*)d_out;

    cudaFuncSetAttribute(attention, cudaFuncAttributeMaxDynamicSharedMemorySize, 62464);

    cvtX<<<4096, 256>>>(hs);
    dim3 gW(512, 1, 3);
    cvtW<<<gW, 256>>>(Wq, Wk, Wv);

    dim3 ggemm(H_ / 128, (B_ * S_) / 128, 3);   // fused Q/K/V
    qkv_gemm<<<ggemm, 256>>>(bq, bk, bv);

    dim3 gattn(S_ / 128, NH_, B_);              // (16, 16, 2)
    attention<<<gattn, 128, 62464>>>(mask, out);
}